// round 2
// baseline (speedup 1.0000x reference)
#include <cuda_runtime.h>
#include <math.h>

#define B_   8192
#define L_   200
#define S_   81
#define SP_  84        /* padded S (16B-aligned rows, odd vec4 stride) */
#define CEN_ 40
#define D_   128
#define H_   4
#define XSZ  (L_*S_)   /* 16200 floats per b */

// ---- scratch (device globals; no allocation allowed) ----
__device__ float g_R[(size_t)B_*H_*L_];      // r vectors  [b][h][l]
__device__ float g_c[(size_t)B_*H_];         // c_h = q_h . bk_h
__device__ float g_central[(size_t)B_*D_];   // central = Wv xs_c + bv
__device__ float g_Y[(size_t)B_*H_*L_];      // y_h[l] = sum_s attn[h,s] xs[s][l]
__device__ float g_sur[(size_t)B_*D_];       // surround

// ============================================================
// kprep: per 64-b tile: gather xs_center, compute Q (=Xc Wq^T + bq),
// central (=Xc Wv^T + bv), then R[b,h,l] = sum_d Wk[h*32+d,l]*Q[b,h*32+d]
// and c[b,h] = q_h . bk_h.
// grid 128, block 256, dyn smem = 26368 floats (105472 B)
// ============================================================
__global__ void __launch_bounds__(256, 2) kprep(
    const float* __restrict__ x,  const float* __restrict__ Wk,
    const float* __restrict__ bk, const float* __restrict__ Wv,
    const float* __restrict__ bv, const float* __restrict__ Wq,
    const float* __restrict__ bq)
{
    extern __shared__ float sm[];
    float* XcT = sm;           // [200][64]  XcT[l*64+bb]
    float* Wb  = sm + 12800;   // [256][53]  chunk of Wq|Wv, row dd, cols kk(0..49)
    const int tid = threadIdx.x;
    const int b0  = blockIdx.x * 64;

    // phase a: gather xs_center (strided)
    for (int idx = tid; idx < 64 * 200; idx += 256) {
        int bb = idx & 63, l = idx >> 6;
        XcT[l * 64 + bb] = x[(size_t)(b0 + bb) * XSZ + l * S_ + CEN_];
    }
    __syncthreads();

    // phase b: 64b x 256d GEMM (d<128 -> Q via Wq, d>=128 -> central via Wv)
    const int bi = tid & 7;    // b-group: b = bi*8 + v
    const int dj = tid >> 3;   // d-group: d = dj*8 + u
    float acc[8][8];
    #pragma unroll
    for (int v = 0; v < 8; v++)
        #pragma unroll
        for (int u = 0; u < 8; u++) acc[v][u] = 0.f;

    const int w = tid >> 5, lane = tid & 31;
    for (int k0 = 0; k0 < 200; k0 += 50) {
        for (int r = 0; r < 32; r++) {
            int dd = w * 32 + r;
            const float* wr = (dd < 128) ? (Wq + dd * L_) : (Wv + (size_t)(dd - 128) * L_);
            Wb[dd * 53 + lane] = wr[k0 + lane];
            if (lane < 18) Wb[dd * 53 + 32 + lane] = wr[k0 + 32 + lane];
        }
        __syncthreads();
        #pragma unroll 2
        for (int kk = 0; kk < 50; kk++) {
            float4 xa0 = *(const float4*)&XcT[(k0 + kk) * 64 + bi * 8];
            float4 xa1 = *(const float4*)&XcT[(k0 + kk) * 64 + bi * 8 + 4];
            float xa[8] = {xa0.x, xa0.y, xa0.z, xa0.w, xa1.x, xa1.y, xa1.z, xa1.w};
            float wv8[8];
            #pragma unroll
            for (int u = 0; u < 8; u++) wv8[u] = Wb[(dj * 8 + u) * 53 + kk];
            #pragma unroll
            for (int v = 0; v < 8; v++)
                #pragma unroll
                for (int u = 0; u < 8; u++)
                    acc[v][u] += xa[v] * wv8[u];
        }
        __syncthreads();
    }

    // epilogue: Q -> smem QT[d][b] (reuses XcT region), central -> global
    float* QT = sm;  // [128][64]
    if (dj < 16) {
        #pragma unroll
        for (int u = 0; u < 8; u++) {
            int d = dj * 8 + u;
            float bqd = bq[d];
            #pragma unroll
            for (int v = 0; v < 8; v++)
                QT[d * 64 + bi * 8 + v] = acc[v][u] + bqd;
        }
    } else {
        #pragma unroll
        for (int u = 0; u < 8; u++) {
            int d = (dj - 16) * 8 + u;
            float bvd = bv[d];
            #pragma unroll
            for (int v = 0; v < 8; v++)
                g_central[(size_t)(b0 + bi * 8 + v) * D_ + d] = acc[v][u] + bvd;
        }
    }
    __syncthreads();

    // c[b,h] = q_h . bk_h
    {
        int bb = tid & 63, h = tid >> 6;
        float cacc = 0.f;
        for (int dd = 0; dd < 32; dd++)
            cacc += QT[(h * 32 + dd) * 64 + bb] * bk[h * 32 + dd];
        g_c[(size_t)(b0 + bb) * H_ + h] = cacc;
    }

    // phase c: R[b,h,l] = sum_{d<32} Wk[h*32+d, l] * Q[b, h*32+d]
    float* Wkc = sm + 8192;        // [128][100] chunk of Wk columns
    const int bi2 = tid >> 5;      // 0..7: b = bi2*8 + v
    for (int lc = 0; lc < 2; lc++) {
        __syncthreads();
        for (int idx = tid; idx < 12800; idx += 256) {
            int dd = idx / 100, ll = idx - dd * 100;
            Wkc[idx] = Wk[(size_t)dd * L_ + lc * 100 + ll];
        }
        __syncthreads();
        for (int h = 0; h < H_; h++) {
            float acc2[8][4];
            #pragma unroll
            for (int v = 0; v < 8; v++)
                #pragma unroll
                for (int jj = 0; jj < 4; jj++) acc2[v][jj] = 0.f;
            for (int d = 0; d < 32; d++) {
                float4 q0 = *(const float4*)&QT[(h * 32 + d) * 64 + bi2 * 8];
                float4 q1 = *(const float4*)&QT[(h * 32 + d) * 64 + bi2 * 8 + 4];
                float q8[8] = {q0.x, q0.y, q0.z, q0.w, q1.x, q1.y, q1.z, q1.w};
                float wk4[4];
                #pragma unroll
                for (int jj = 0; jj < 4; jj++) {
                    int ll = lane + 32 * jj;
                    wk4[jj] = (ll < 100) ? Wkc[(h * 32 + d) * 100 + ll] : 0.f;
                }
                #pragma unroll
                for (int v = 0; v < 8; v++)
                    #pragma unroll
                    for (int jj = 0; jj < 4; jj++)
                        acc2[v][jj] += q8[v] * wk4[jj];
            }
            #pragma unroll
            for (int jj = 0; jj < 4; jj++) {
                int ll = lane + 32 * jj;
                if (ll < 100) {
                    int l = lc * 100 + ll;
                    #pragma unroll
                    for (int v = 0; v < 8; v++)
                        g_R[(size_t)(b0 + bi2 * 8 + v) * (H_ * L_) + h * L_ + l] = acc2[v][jj];
                }
            }
        }
    }
}

// ============================================================
// kmain (rewritten, register-tiled):
//   smem xs padded [200][84]; scores via per-thread 4s x 4h tiles
//   (1 LDS.128 + 4 bcast per 16 FMA, xs read once); softmax; y via
//   per-thread l x 4h vec4 tiles. One b per block, 256 threads.
//   dyn smem = 21972 floats (87888 B)
// ============================================================
#define NCH_ 12            /* l-chunks in scores phase */
#define LPC_ 17            /* l per chunk (12*17 >= 200) */

__global__ void __launch_bounds__(256, 2) kmain(const float* __restrict__ x)
{
    extern __shared__ float sm[];
    float* xs   = sm;            // [200][84]
    float* Rs   = sm + 16800;    // [4][200]
    float* cs   = Rs + 800;      // [4]
    float* sc   = cs + 4;        // [4][84]  scores -> attn in place
    float* part = sc + 336;      // [12][4][84]
    const int tid = threadIdx.x;
    const int b = blockIdx.x;

    // ---- load x[b] -> padded smem (vec4 gmem loads) ----
    {
        const float4* xb = (const float4*)(x + (size_t)b * XSZ);
        for (int i4 = tid; i4 < XSZ / 4; i4 += 256) {
            float4 v = xb[i4];
            int e = i4 * 4;
            int l = e / 81, s = e - l * 81;
            float vv[4] = {v.x, v.y, v.z, v.w};
            #pragma unroll
            for (int j = 0; j < 4; j++) {
                xs[l * SP_ + s] = vv[j];
                if (++s == 81) { s = 0; ++l; }
            }
        }
        for (int i = tid; i < 800; i += 256)
            Rs[i] = g_R[(size_t)b * 800 + i];
        if (tid < 4) cs[tid] = g_c[(size_t)b * 4 + tid];
    }
    __syncthreads();

    // ---- phase 1: partial scores. thread = (s4 = 4*(tid%21), chunk = tid/21) ----
    if (tid < 21 * NCH_) {
        const int s4 = (tid % 21) * 4;
        const int ch = tid / 21;
        const int l0 = ch * LPC_;
        const int l1 = (l0 + LPC_ < 200) ? l0 + LPC_ : 200;
        float a[H_][4];
        #pragma unroll
        for (int h = 0; h < H_; h++)
            #pragma unroll
            for (int j = 0; j < 4; j++) a[h][j] = 0.f;
        for (int l = l0; l < l1; l++) {
            float4 xv = *(const float4*)&xs[l * SP_ + s4];
            float r0 = Rs[l], r1 = Rs[200 + l], r2 = Rs[400 + l], r3 = Rs[600 + l];
            a[0][0] += r0 * xv.x; a[0][1] += r0 * xv.y; a[0][2] += r0 * xv.z; a[0][3] += r0 * xv.w;
            a[1][0] += r1 * xv.x; a[1][1] += r1 * xv.y; a[1][2] += r1 * xv.z; a[1][3] += r1 * xv.w;
            a[2][0] += r2 * xv.x; a[2][1] += r2 * xv.y; a[2][2] += r2 * xv.z; a[2][3] += r2 * xv.w;
            a[3][0] += r3 * xv.x; a[3][1] += r3 * xv.y; a[3][2] += r3 * xv.z; a[3][3] += r3 * xv.w;
        }
        #pragma unroll
        for (int h = 0; h < H_; h++) {
            float4 o = make_float4(a[h][0], a[h][1], a[h][2], a[h][3]);
            *(float4*)&part[(ch * H_ + h) * SP_ + s4] = o;
        }
    }
    __syncthreads();

    // ---- reduce partials -> scores (scaled, masked) ----
    for (int o = tid; o < H_ * SP_; o += 256) {
        int h = o / SP_, s = o - h * SP_;
        float v = 0.f;
        #pragma unroll
        for (int c = 0; c < NCH_; c++) v += part[(c * H_ + h) * SP_ + s];
        v = (v + cs[h]) * 0.0883883476483184405f;
        if (s == CEN_) v += -1000000.0f;
        if (s >= 81) v = -INFINITY;
        sc[o] = v;
    }
    __syncthreads();

    // ---- softmax (warp h handles row h; rows are 84 wide, s>=81 = -inf -> 0) ----
    const int wid = tid >> 5, lane = tid & 31;
    if (wid < 4) {
        float v0 = sc[wid * SP_ + lane];
        float v1 = sc[wid * SP_ + 32 + lane];
        float v2 = (lane < 20) ? sc[wid * SP_ + 64 + lane] : -INFINITY;
        float m = fmaxf(v0, fmaxf(v1, v2));
        #pragma unroll
        for (int o = 16; o > 0; o >>= 1) m = fmaxf(m, __shfl_xor_sync(0xffffffffu, m, o));
        float e0 = __expf(v0 - m), e1 = __expf(v1 - m);
        float e2 = (lane < 20 && v2 > -INFINITY) ? __expf(v2 - m) : 0.f;
        float s3 = e0 + e1 + e2;
        #pragma unroll
        for (int o = 16; o > 0; o >>= 1) s3 += __shfl_xor_sync(0xffffffffu, s3, o);
        float rs = 1.f / s3;
        sc[wid * SP_ + lane] = e0 * rs;
        sc[wid * SP_ + 32 + lane] = e1 * rs;
        if (lane < 20) sc[wid * SP_ + 64 + lane] = e2 * rs;
    }
    __syncthreads();

    // ---- phase 2: y[h][l] = sum_s attn[h][s]*xs[l][s], thread = l ----
    if (tid < 200) {
        const float* xr = xs + tid * SP_;
        float a0 = 0.f, a1 = 0.f, a2 = 0.f, a3 = 0.f;
        #pragma unroll 3
        for (int c = 0; c < 21; c++) {
            float4 xv = *(const float4*)&xr[c * 4];
            float4 t0 = *(const float4*)&sc[0 * SP_ + c * 4];
            float4 t1 = *(const float4*)&sc[1 * SP_ + c * 4];
            float4 t2 = *(const float4*)&sc[2 * SP_ + c * 4];
            float4 t3 = *(const float4*)&sc[3 * SP_ + c * 4];
            a0 += t0.x * xv.x + t0.y * xv.y + t0.z * xv.z + t0.w * xv.w;
            a1 += t1.x * xv.x + t1.y * xv.y + t1.z * xv.z + t1.w * xv.w;
            a2 += t2.x * xv.x + t2.y * xv.y + t2.z * xv.z + t2.w * xv.w;
            a3 += t3.x * xv.x + t3.y * xv.y + t3.z * xv.z + t3.w * xv.w;
        }
        float* Yb = g_Y + (size_t)b * 800;
        Yb[tid] = a0; Yb[200 + tid] = a1; Yb[400 + tid] = a2; Yb[600 + tid] = a3;
    }
}

// ============================================================
// ksur: surround[b, h*32+d] = sum_l Wv[h*32+d,l]*Y[b,h,l] + bv
// grid (128,4), block 256, dyn smem = 20000 floats (80000 B)
// ============================================================
__global__ void __launch_bounds__(256, 2) ksur(const float* __restrict__ Wv,
                                               const float* __restrict__ bv)
{
    extern __shared__ float sm[];
    float* YT  = sm;            // [200][68] (padded)
    float* Wvs = sm + 13600;    // [32][200]
    const int tid = threadIdx.x;
    const int b0 = blockIdx.x * 64;
    const int h  = blockIdx.y;
    const int lane = tid & 31, w = tid >> 5;

    for (int rb = 0; rb < 8; rb++) {
        int bb = w * 8 + rb;
        const float* ysrc = g_Y + (size_t)(b0 + bb) * 800 + h * 200;
        #pragma unroll
        for (int t = 0; t < 7; t++) {
            int l = lane + 32 * t;
            if (l < 200) YT[l * 68 + bb] = ysrc[l];
        }
    }
    for (int idx = tid; idx < 32 * 200; idx += 256)
        Wvs[idx] = Wv[(size_t)(h * 32) * L_ + idx];
    __syncthreads();

    const int bi = tid & 7;    // b = bi*8 + v
    const int dj = tid >> 3;   // d = dj (0..31)
    float acc[8];
    #pragma unroll
    for (int v = 0; v < 8; v++) acc[v] = 0.f;
    for (int l = 0; l < 200; l++) {
        float wv = Wvs[dj * 200 + l];
        float4 y0 = *(const float4*)&YT[l * 68 + bi * 8];
        float4 y1 = *(const float4*)&YT[l * 68 + bi * 8 + 4];
        acc[0] += wv * y0.x; acc[1] += wv * y0.y; acc[2] += wv * y0.z; acc[3] += wv * y0.w;
        acc[4] += wv * y1.x; acc[5] += wv * y1.y; acc[6] += wv * y1.z; acc[7] += wv * y1.w;
    }
    float bvd = bv[h * 32 + dj];
    #pragma unroll
    for (int v = 0; v < 8; v++)
        g_sur[(size_t)(b0 + bi * 8 + v) * D_ + h * 32 + dj] = acc[v] + bvd;
}

// ============================================================
// kgate
// ============================================================
__global__ void __launch_bounds__(256) kgate(const float* __restrict__ Wg,
                                             const float* __restrict__ bg,
                                             float* __restrict__ out)
{
    const int lane = threadIdx.x & 31, w = threadIdx.x >> 5;
    const int b = blockIdx.x * 8 + w;
    float4 c4 = *(const float4*)&g_central[(size_t)b * D_ + lane * 4];
    float4 s4 = *(const float4*)&g_sur[(size_t)b * D_ + lane * 4];
    float4 w4 = *(const float4*)&Wg[lane * 4];
    float dot = (c4.x - s4.x) * w4.x + (c4.y - s4.y) * w4.y +
                (c4.z - s4.z) * w4.z + (c4.w - s4.w) * w4.w;
    #pragma unroll
    for (int o = 16; o > 0; o >>= 1) dot += __shfl_xor_sync(0xffffffffu, dot, o);
    float g = 1.f / (1.f + expf(-(dot + bg[0])));
    float4 o4;
    o4.x = c4.x + g * s4.x; o4.y = c4.y + g * s4.y;
    o4.z = c4.z + g * s4.z; o4.w = c4.w + g * s4.w;
    *(float4*)&out[(size_t)b * D_ + lane * 4] = o4;
}

extern "C" void kernel_launch(void* const* d_in, const int* in_sizes, int n_in,
                              void* d_out, int out_size)
{
    const float* x  = (const float*)d_in[0];
    const float* Wk = (const float*)d_in[1];
    const float* bk = (const float*)d_in[2];
    const float* Wv = (const float*)d_in[3];
    const float* bv = (const float*)d_in[4];
    const float* Wq = (const float*)d_in[5];
    const float* bq = (const float*)d_in[6];
    const float* Wg = (const float*)d_in[7];
    const float* bg = (const float*)d_in[8];
    float* out = (float*)d_out;

    cudaFuncSetAttribute(kprep, cudaFuncAttributeMaxDynamicSharedMemorySize, 105472);
    cudaFuncSetAttribute(kmain, cudaFuncAttributeMaxDynamicSharedMemorySize, 87888);
    cudaFuncSetAttribute(ksur,  cudaFuncAttributeMaxDynamicSharedMemorySize, 80000);

    kprep<<<128, 256, 105472>>>(x, Wk, bk, Wv, bv, Wq, bq);
    kmain<<<8192, 256, 87888>>>(x);
    ksur<<<dim3(128, 4), 256, 80000>>>(Wv, bv);
    kgate<<<1024, 256>>>(Wg, bg, out);
}

// round 4
// speedup vs baseline: 1.1701x; 1.1701x over previous
#include <cuda_runtime.h>
#include <math.h>

#define B_   8192
#define L_   200
#define S_   81
#define SP_  84        /* padded S (16B-aligned rows) */
#define CEN_ 40
#define D_   128
#define H_   4
#define XSZ  (L_*S_)   /* 16200 floats per b */

// ---- scratch (device globals; no allocation allowed) ----
__device__ float g_R[(size_t)B_*H_*L_];
__device__ float g_c[(size_t)B_*H_];
__device__ float g_central[(size_t)B_*D_];
__device__ float g_Y[(size_t)B_*H_*L_];
__device__ float g_sur[(size_t)B_*D_];
__device__ float g_dummy;

// tiny no-op kernels: shift the ncu -s 5 capture window onto kmain
__global__ void knop() { if (threadIdx.x == 0) g_dummy = 1.0f; }

// ============================================================
// kprep (unchanged): Q, central, R, c per 64-b tile
// ============================================================
__global__ void __launch_bounds__(256, 2) kprep(
    const float* __restrict__ x,  const float* __restrict__ Wk,
    const float* __restrict__ bk, const float* __restrict__ Wv,
    const float* __restrict__ bv, const float* __restrict__ Wq,
    const float* __restrict__ bq)
{
    extern __shared__ float sm[];
    float* XcT = sm;           // [200][64]
    float* Wb  = sm + 12800;   // [256][53]
    const int tid = threadIdx.x;
    const int b0  = blockIdx.x * 64;

    for (int idx = tid; idx < 64 * 200; idx += 256) {
        int bb = idx & 63, l = idx >> 6;
        XcT[l * 64 + bb] = x[(size_t)(b0 + bb) * XSZ + l * S_ + CEN_];
    }
    __syncthreads();

    const int bi = tid & 7;
    const int dj = tid >> 3;
    float acc[8][8];
    #pragma unroll
    for (int v = 0; v < 8; v++)
        #pragma unroll
        for (int u = 0; u < 8; u++) acc[v][u] = 0.f;

    const int w = tid >> 5, lane = tid & 31;
    for (int k0 = 0; k0 < 200; k0 += 50) {
        for (int r = 0; r < 32; r++) {
            int dd = w * 32 + r;
            const float* wr = (dd < 128) ? (Wq + dd * L_) : (Wv + (size_t)(dd - 128) * L_);
            Wb[dd * 53 + lane] = wr[k0 + lane];
            if (lane < 18) Wb[dd * 53 + 32 + lane] = wr[k0 + 32 + lane];
        }
        __syncthreads();
        #pragma unroll 2
        for (int kk = 0; kk < 50; kk++) {
            float4 xa0 = *(const float4*)&XcT[(k0 + kk) * 64 + bi * 8];
            float4 xa1 = *(const float4*)&XcT[(k0 + kk) * 64 + bi * 8 + 4];
            float xa[8] = {xa0.x, xa0.y, xa0.z, xa0.w, xa1.x, xa1.y, xa1.z, xa1.w};
            float wv8[8];
            #pragma unroll
            for (int u = 0; u < 8; u++) wv8[u] = Wb[(dj * 8 + u) * 53 + kk];
            #pragma unroll
            for (int v = 0; v < 8; v++)
                #pragma unroll
                for (int u = 0; u < 8; u++)
                    acc[v][u] += xa[v] * wv8[u];
        }
        __syncthreads();
    }

    float* QT = sm;  // [128][64]
    if (dj < 16) {
        #pragma unroll
        for (int u = 0; u < 8; u++) {
            int d = dj * 8 + u;
            float bqd = bq[d];
            #pragma unroll
            for (int v = 0; v < 8; v++)
                QT[d * 64 + bi * 8 + v] = acc[v][u] + bqd;
        }
    } else {
        #pragma unroll
        for (int u = 0; u < 8; u++) {
            int d = (dj - 16) * 8 + u;
            float bvd = bv[d];
            #pragma unroll
            for (int v = 0; v < 8; v++)
                g_central[(size_t)(b0 + bi * 8 + v) * D_ + d] = acc[v][u] + bvd;
        }
    }
    __syncthreads();

    {
        int bb = tid & 63, h = tid >> 6;
        float cacc = 0.f;
        for (int dd = 0; dd < 32; dd++)
            cacc += QT[(h * 32 + dd) * 64 + bb] * bk[h * 32 + dd];
        g_c[(size_t)(b0 + bb) * H_ + h] = cacc;
    }

    float* Wkc = sm + 8192;        // [128][100]
    const int bi2 = tid >> 5;
    for (int lc = 0; lc < 2; lc++) {
        __syncthreads();
        for (int idx = tid; idx < 12800; idx += 256) {
            int dd = idx / 100, ll = idx - dd * 100;
            Wkc[idx] = Wk[(size_t)dd * L_ + lc * 100 + ll];
        }
        __syncthreads();
        for (int h = 0; h < H_; h++) {
            float acc2[8][4];
            #pragma unroll
            for (int v = 0; v < 8; v++)
                #pragma unroll
                for (int jj = 0; jj < 4; jj++) acc2[v][jj] = 0.f;
            for (int d = 0; d < 32; d++) {
                float4 q0 = *(const float4*)&QT[(h * 32 + d) * 64 + bi2 * 8];
                float4 q1 = *(const float4*)&QT[(h * 32 + d) * 64 + bi2 * 8 + 4];
                float q8[8] = {q0.x, q0.y, q0.z, q0.w, q1.x, q1.y, q1.z, q1.w};
                float wk4[4];
                #pragma unroll
                for (int jj = 0; jj < 4; jj++) {
                    int ll = lane + 32 * jj;
                    wk4[jj] = (ll < 100) ? Wkc[(h * 32 + d) * 100 + ll] : 0.f;
                }
                #pragma unroll
                for (int v = 0; v < 8; v++)
                    #pragma unroll
                    for (int jj = 0; jj < 4; jj++)
                        acc2[v][jj] += q8[v] * wk4[jj];
            }
            #pragma unroll
            for (int jj = 0; jj < 4; jj++) {
                int ll = lane + 32 * jj;
                if (ll < 100) {
                    int l = lc * 100 + ll;
                    #pragma unroll
                    for (int v = 0; v < 8; v++)
                        g_R[(size_t)(b0 + bi2 * 8 + v) * (H_ * L_) + h * L_ + l] = acc2[v][jj];
                }
            }
        }
    }
}

// ============================================================
// kmain v3b: warp-safe vec4 scores with shfl c-reduction.
// block 416, dyn smem = 17940 floats (71760 B), 3 CTAs/SM
// ============================================================
__global__ void __launch_bounds__(416, 3) kmain(const float* __restrict__ x)
{
    extern __shared__ float sm[];
    float* xs = sm;            // [200][84]   (0..16799)
    float* Rs = sm + 16800;    // [4][200]    (16800..17599)
    float* cs = Rs + 800;      // [4]         (17600..17603)
    float* sc = cs + 4;        // [4][84]     (17604..17939) scores->attn
    const int tid = threadIdx.x;
    const size_t b = blockIdx.x;

    // ---- load x[b] -> padded smem; zero row padding ----
    {
        const float4* xb = (const float4*)(x + b * XSZ);
        for (int i4 = tid; i4 < XSZ / 4; i4 += 416) {
            float4 v = xb[i4];
            int e = i4 * 4;
            int l = e / 81, s = e - l * 81;
            float vv[4] = {v.x, v.y, v.z, v.w};
            #pragma unroll
            for (int j = 0; j < 4; j++) {
                xs[l * SP_ + s] = vv[j];
                if (++s == 81) { s = 0; ++l; }
            }
        }
        if (tid < 200) {
            xs[tid * SP_ + 81] = 0.f;
            xs[tid * SP_ + 82] = 0.f;
            xs[tid * SP_ + 83] = 0.f;
        }
        for (int i = tid; i < 800; i += 416)
            Rs[i] = g_R[b * 800 + i];
        if (tid < 4) cs[tid] = g_c[b * 4 + tid];
    }
    __syncthreads();

    // ---- scores: 12 FULL warps (tid<384). group g=tid/4 in [0,96),
    //      c=tid&3 (l-chunk of 50), h=g/24, sq=g%24 (sq>=21 -> dummy) ----
    if (tid < 384) {
        const int g  = tid >> 2;
        const int c  = tid & 3;
        const int h  = g / 24;
        const int sq = g - h * 24;
        // clamp dummy groups' read column into range (results discarded)
        const int s4r = (sq < 21) ? sq * 4 : 76;
        const float* rh = Rs + h * 200;
        const int l0 = c * 50;
        float a0 = 0.f, a1 = 0.f, a2 = 0.f, a3 = 0.f;
        #pragma unroll 5
        for (int l = l0; l < l0 + 50; l++) {
            float4 xv = *(const float4*)&xs[l * SP_ + s4r];
            float rv = rh[l];
            a0 += rv * xv.x; a1 += rv * xv.y; a2 += rv * xv.z; a3 += rv * xv.w;
        }
        // reduce across c (lane bits 0-1); all 32 lanes of each warp active
        const unsigned m = 0xffffffffu;
        a0 += __shfl_xor_sync(m, a0, 1); a0 += __shfl_xor_sync(m, a0, 2);
        a1 += __shfl_xor_sync(m, a1, 1); a1 += __shfl_xor_sync(m, a1, 2);
        a2 += __shfl_xor_sync(m, a2, 1); a2 += __shfl_xor_sync(m, a2, 2);
        a3 += __shfl_xor_sync(m, a3, 1); a3 += __shfl_xor_sync(m, a3, 2);
        if (c == 0 && sq < 21) {
            const int s4 = sq * 4;
            float ch = cs[h];
            float vv[4] = {a0, a1, a2, a3};
            float4 o;
            float* op = (float*)&o;
            #pragma unroll
            for (int j = 0; j < 4; j++) {
                int s = s4 + j;
                float v = (vv[j] + ch) * 0.0883883476483184405f;
                if (s == CEN_) v += -1000000.0f;
                if (s >= 81)  v = -INFINITY;
                op[j] = v;
            }
            *(float4*)&sc[h * SP_ + s4] = o;
        }
    }
    __syncthreads();

    // ---- softmax: warp h handles row h (full warps) ----
    const int wid = tid >> 5, lane = tid & 31;
    if (wid < 4) {
        float v0 = sc[wid * SP_ + lane];
        float v1 = sc[wid * SP_ + 32 + lane];
        float v2 = (lane < 20) ? sc[wid * SP_ + 64 + lane] : -INFINITY;
        float mx = fmaxf(v0, fmaxf(v1, v2));
        #pragma unroll
        for (int o = 16; o > 0; o >>= 1) mx = fmaxf(mx, __shfl_xor_sync(0xffffffffu, mx, o));
        float e0 = __expf(v0 - mx), e1 = __expf(v1 - mx);
        float e2 = (lane < 20 && v2 > -INFINITY) ? __expf(v2 - mx) : 0.f;
        float s3 = e0 + e1 + e2;
        #pragma unroll
        for (int o = 16; o > 0; o >>= 1) s3 += __shfl_xor_sync(0xffffffffu, s3, o);
        float rs = 1.f / s3;
        sc[wid * SP_ + lane] = e0 * rs;
        sc[wid * SP_ + 32 + lane] = e1 * rs;
        if (lane < 20) sc[wid * SP_ + 64 + lane] = e2 * rs;
    }
    __syncthreads();

    // ---- y: thread = (head-pair, l); xs row read once per pair ----
    if (tid < 400) {
        const int hp = tid / 200;        // 0: h0,h1  1: h2,h3
        const int l  = tid - hp * 200;
        const float* xr = xs + l * SP_;
        const float* A0 = sc + (hp * 2) * SP_;
        const float* A1 = A0 + SP_;
        float a0 = 0.f, a1 = 0.f;
        #pragma unroll 7
        for (int c = 0; c < 21; c++) {
            float4 xv = *(const float4*)&xr[c * 4];
            float4 t0 = *(const float4*)&A0[c * 4];
            float4 t1 = *(const float4*)&A1[c * 4];
            a0 += t0.x * xv.x + t0.y * xv.y + t0.z * xv.z + t0.w * xv.w;
            a1 += t1.x * xv.x + t1.y * xv.y + t1.z * xv.z + t1.w * xv.w;
        }
        float* Yb = g_Y + b * 800 + hp * 400;
        Yb[l] = a0;
        Yb[200 + l] = a1;
    }
}

// ============================================================
// ksur (unchanged)
// ============================================================
__global__ void __launch_bounds__(256, 2) ksur(const float* __restrict__ Wv,
                                               const float* __restrict__ bv)
{
    extern __shared__ float sm[];
    float* YT  = sm;            // [200][68]
    float* Wvs = sm + 13600;    // [32][200]
    const int tid = threadIdx.x;
    const int b0 = blockIdx.x * 64;
    const int h  = blockIdx.y;
    const int lane = tid & 31, w = tid >> 5;

    for (int rb = 0; rb < 8; rb++) {
        int bb = w * 8 + rb;
        const float* ysrc = g_Y + (size_t)(b0 + bb) * 800 + h * 200;
        #pragma unroll
        for (int t = 0; t < 7; t++) {
            int l = lane + 32 * t;
            if (l < 200) YT[l * 68 + bb] = ysrc[l];
        }
    }
    for (int idx = tid; idx < 32 * 200; idx += 256)
        Wvs[idx] = Wv[(size_t)(h * 32) * L_ + idx];
    __syncthreads();

    const int bi = tid & 7;
    const int dj = tid >> 3;
    float acc[8];
    #pragma unroll
    for (int v = 0; v < 8; v++) acc[v] = 0.f;
    for (int l = 0; l < 200; l++) {
        float wv = Wvs[dj * 200 + l];
        float4 y0 = *(const float4*)&YT[l * 68 + bi * 8];
        float4 y1 = *(const float4*)&YT[l * 68 + bi * 8 + 4];
        acc[0] += wv * y0.x; acc[1] += wv * y0.y; acc[2] += wv * y0.z; acc[3] += wv * y0.w;
        acc[4] += wv * y1.x; acc[5] += wv * y1.y; acc[6] += wv * y1.z; acc[7] += wv * y1.w;
    }
    float bvd = bv[h * 32 + dj];
    #pragma unroll
    for (int v = 0; v < 8; v++)
        g_sur[(size_t)(b0 + bi * 8 + v) * D_ + h * 32 + dj] = acc[v] + bvd;
}

// ============================================================
// kgate (unchanged)
// ============================================================
__global__ void __launch_bounds__(256) kgate(const float* __restrict__ Wg,
                                             const float* __restrict__ bg,
                                             float* __restrict__ out)
{
    const int lane = threadIdx.x & 31, w = threadIdx.x >> 5;
    const int b = blockIdx.x * 8 + w;
    float4 c4 = *(const float4*)&g_central[(size_t)b * D_ + lane * 4];
    float4 s4 = *(const float4*)&g_sur[(size_t)b * D_ + lane * 4];
    float4 w4 = *(const float4*)&Wg[lane * 4];
    float dot = (c4.x - s4.x) * w4.x + (c4.y - s4.y) * w4.y +
                (c4.z - s4.z) * w4.z + (c4.w - s4.w) * w4.w;
    #pragma unroll
    for (int o = 16; o > 0; o >>= 1) dot += __shfl_xor_sync(0xffffffffu, dot, o);
    float g = 1.f / (1.f + expf(-(dot + bg[0])));
    float4 o4;
    o4.x = c4.x + g * s4.x; o4.y = c4.y + g * s4.y;
    o4.z = c4.z + g * s4.z; o4.w = c4.w + g * s4.w;
    *(float4*)&out[(size_t)b * D_ + lane * 4] = o4;
}

extern "C" void kernel_launch(void* const* d_in, const int* in_sizes, int n_in,
                              void* d_out, int out_size)
{
    const float* x  = (const float*)d_in[0];
    const float* Wk = (const float*)d_in[1];
    const float* bk = (const float*)d_in[2];
    const float* Wv = (const float*)d_in[3];
    const float* bv = (const float*)d_in[4];
    const float* Wq = (const float*)d_in[5];
    const float* bq = (const float*)d_in[6];
    const float* Wg = (const float*)d_in[7];
    const float* bg = (const float*)d_in[8];
    float* out = (float*)d_out;

    cudaFuncSetAttribute(kprep, cudaFuncAttributeMaxDynamicSharedMemorySize, 105472);
    cudaFuncSetAttribute(kmain, cudaFuncAttributeMaxDynamicSharedMemorySize, 71760);
    cudaFuncSetAttribute(ksur,  cudaFuncAttributeMaxDynamicSharedMemorySize, 80000);

    // two no-op launches: shift ncu's -s 5 window so slot 6 == kmain
    knop<<<1, 32>>>();
    knop<<<1, 32>>>();
    kprep<<<128, 256, 105472>>>(x, Wk, bk, Wv, bv, Wq, bq);
    kmain<<<8192, 416, 71760>>>(x);
    ksur<<<dim3(128, 4), 256, 80000>>>(Wv, bv);
    kgate<<<1024, 256>>>(Wg, bg, out);
}

// round 5
// speedup vs baseline: 1.2856x; 1.0986x over previous
#include <cuda_runtime.h>
#include <math.h>

#define B_   8192
#define L_   200
#define S_   81
#define SP_  84        /* padded row stride (mult of 4 -> aligned LDS.128) */
#define CEN_ 40
#define D_   128
#define H_   4
#define XSZ  (L_*S_)   /* 16200 floats per b */

// ---- scratch (device globals; no allocation allowed) ----
__device__ float g_R[(size_t)B_*H_*L_];
__device__ float g_c[(size_t)B_*H_];
__device__ float g_central[(size_t)B_*D_];
__device__ float g_Y[(size_t)B_*H_*L_];
__device__ float g_sur[(size_t)B_*D_];
__device__ float g_dummy;

// tiny no-op kernels: keep ncu -s 5 window on kmain (slot 6)
__global__ void knop() { if (threadIdx.x == 0) g_dummy = 1.0f; }

// ============================================================
// kprep (unchanged): Q, central, R, c per 64-b tile
// ============================================================
__global__ void __launch_bounds__(256, 2) kprep(
    const float* __restrict__ x,  const float* __restrict__ Wk,
    const float* __restrict__ bk, const float* __restrict__ Wv,
    const float* __restrict__ bv, const float* __restrict__ Wq,
    const float* __restrict__ bq)
{
    extern __shared__ float sm[];
    float* XcT = sm;           // [200][64]
    float* Wb  = sm + 12800;   // [256][53]
    const int tid = threadIdx.x;
    const int b0  = blockIdx.x * 64;

    for (int idx = tid; idx < 64 * 200; idx += 256) {
        int bb = idx & 63, l = idx >> 6;
        XcT[l * 64 + bb] = x[(size_t)(b0 + bb) * XSZ + l * S_ + CEN_];
    }
    __syncthreads();

    const int bi = tid & 7;
    const int dj = tid >> 3;
    float acc[8][8];
    #pragma unroll
    for (int v = 0; v < 8; v++)
        #pragma unroll
        for (int u = 0; u < 8; u++) acc[v][u] = 0.f;

    const int w = tid >> 5, lane = tid & 31;
    for (int k0 = 0; k0 < 200; k0 += 50) {
        for (int r = 0; r < 32; r++) {
            int dd = w * 32 + r;
            const float* wr = (dd < 128) ? (Wq + dd * L_) : (Wv + (size_t)(dd - 128) * L_);
            Wb[dd * 53 + lane] = wr[k0 + lane];
            if (lane < 18) Wb[dd * 53 + 32 + lane] = wr[k0 + 32 + lane];
        }
        __syncthreads();
        #pragma unroll 2
        for (int kk = 0; kk < 50; kk++) {
            float4 xa0 = *(const float4*)&XcT[(k0 + kk) * 64 + bi * 8];
            float4 xa1 = *(const float4*)&XcT[(k0 + kk) * 64 + bi * 8 + 4];
            float xa[8] = {xa0.x, xa0.y, xa0.z, xa0.w, xa1.x, xa1.y, xa1.z, xa1.w};
            float wv8[8];
            #pragma unroll
            for (int u = 0; u < 8; u++) wv8[u] = Wb[(dj * 8 + u) * 53 + kk];
            #pragma unroll
            for (int v = 0; v < 8; v++)
                #pragma unroll
                for (int u = 0; u < 8; u++)
                    acc[v][u] += xa[v] * wv8[u];
        }
        __syncthreads();
    }

    float* QT = sm;  // [128][64]
    if (dj < 16) {
        #pragma unroll
        for (int u = 0; u < 8; u++) {
            int d = dj * 8 + u;
            float bqd = bq[d];
            #pragma unroll
            for (int v = 0; v < 8; v++)
                QT[d * 64 + bi * 8 + v] = acc[v][u] + bqd;
        }
    } else {
        #pragma unroll
        for (int u = 0; u < 8; u++) {
            int d = (dj - 16) * 8 + u;
            float bvd = bv[d];
            #pragma unroll
            for (int v = 0; v < 8; v++)
                g_central[(size_t)(b0 + bi * 8 + v) * D_ + d] = acc[v][u] + bvd;
        }
    }
    __syncthreads();

    {
        int bb = tid & 63, h = tid >> 6;
        float cacc = 0.f;
        for (int dd = 0; dd < 32; dd++)
            cacc += QT[(h * 32 + dd) * 64 + bb] * bk[h * 32 + dd];
        g_c[(size_t)(b0 + bb) * H_ + h] = cacc;
    }

    float* Wkc = sm + 8192;        // [128][100]
    const int bi2 = tid >> 5;
    for (int lc = 0; lc < 2; lc++) {
        __syncthreads();
        for (int idx = tid; idx < 12800; idx += 256) {
            int dd = idx / 100, ll = idx - dd * 100;
            Wkc[idx] = Wk[(size_t)dd * L_ + lc * 100 + ll];
        }
        __syncthreads();
        for (int h = 0; h < H_; h++) {
            float acc2[8][4];
            #pragma unroll
            for (int v = 0; v < 8; v++)
                #pragma unroll
                for (int jj = 0; jj < 4; jj++) acc2[v][jj] = 0.f;
            for (int d = 0; d < 32; d++) {
                float4 q0 = *(const float4*)&QT[(h * 32 + d) * 64 + bi2 * 8];
                float4 q1 = *(const float4*)&QT[(h * 32 + d) * 64 + bi2 * 8 + 4];
                float q8[8] = {q0.x, q0.y, q0.z, q0.w, q1.x, q1.y, q1.z, q1.w};
                float wk4[4];
                #pragma unroll
                for (int jj = 0; jj < 4; jj++) {
                    int ll = lane + 32 * jj;
                    wk4[jj] = (ll < 100) ? Wkc[(h * 32 + d) * 100 + ll] : 0.f;
                }
                #pragma unroll
                for (int v = 0; v < 8; v++)
                    #pragma unroll
                    for (int jj = 0; jj < 4; jj++)
                        acc2[v][jj] += q8[v] * wk4[jj];
            }
            #pragma unroll
            for (int jj = 0; jj < 4; jj++) {
                int ll = lane + 32 * jj;
                if (ll < 100) {
                    int l = lc * 100 + ll;
                    #pragma unroll
                    for (int v = 0; v < 8; v++)
                        g_R[(size_t)(b0 + bi2 * 8 + v) * (H_ * L_) + h * L_ + l] = acc2[v][jj];
                }
            }
        }
    }
}

// ============================================================
// kmain v4: conflict-free scalar x->smem; 3-warp multi-h scores
// (xs read 1.14x); single-pass y (xs read 1x).
// block 256, dyn smem = 17940 floats (71760 B), 3 CTAs/SM
// ============================================================
__global__ void __launch_bounds__(256, 3) kmain(const float* __restrict__ x)
{
    extern __shared__ float sm[];
    float* xs = sm;            // [200][84]
    float* Rs = sm + 16800;    // [4][200]
    float* cs = Rs + 800;      // [4]
    float* sc = cs + 4;        // [4][84]  scores -> attn in place
    const int tid = threadIdx.x;
    const size_t b = blockIdx.x;

    // ---- load x[b] -> padded smem: lane-consecutive scalar (coalesced LDG,
    //      stride-1 STS, conflict-free). 16200 = 63*256 + 72. ----
    {
        const float* xg = x + b * XSZ + tid;
        int l = tid / 81;
        int s = tid - l * 81;
        int off = l * SP_ + s;
        #pragma unroll 7
        for (int it = 0; it < 63; ++it) {
            xs[off] = xg[it * 256];
            s += 13;                      // 256 = 3*81 + 13
            if (s >= 81) { s -= 81; off += 268; }
            else         {           off += 265; }
        }
        if (tid < 72) xs[off] = xg[63 * 256];

        if (tid < 200) {
            xs[tid * SP_ + 81] = 0.f;
            xs[tid * SP_ + 82] = 0.f;
            xs[tid * SP_ + 83] = 0.f;
        }
        for (int i = tid; i < 800; i += 256)
            Rs[i] = g_R[b * 800 + i];
        if (tid < 4) cs[tid] = g_c[b * 4 + tid];
    }
    __syncthreads();

    // ---- scores: 3 FULL warps. thread = (sq = tid>>2 in [0,24), c = tid&3).
    //      Each thread accumulates ALL 4 heads for its 4 s-columns over 50 l.
    //      sq >= 21 are dummies (read clamped col 80, results discarded). ----
    if (tid < 96) {
        const int sq = tid >> 2;
        const int c  = tid & 3;
        const int s4 = (sq < 21) ? sq * 4 : 80;   // 80..83 valid (pad zeroed)
        const float* xp = xs + c * 50 * SP_ + s4;
        const float* r0p = Rs + c * 50;
        float a[H_][4];
        #pragma unroll
        for (int h = 0; h < H_; h++)
            #pragma unroll
            for (int j = 0; j < 4; j++) a[h][j] = 0.f;
        #pragma unroll 5
        for (int l = 0; l < 50; l++) {
            float4 xv = *(const float4*)xp;
            float r0 = r0p[l], r1 = r0p[200 + l], r2 = r0p[400 + l], r3 = r0p[600 + l];
            a[0][0] += r0 * xv.x; a[0][1] += r0 * xv.y; a[0][2] += r0 * xv.z; a[0][3] += r0 * xv.w;
            a[1][0] += r1 * xv.x; a[1][1] += r1 * xv.y; a[1][2] += r1 * xv.z; a[1][3] += r1 * xv.w;
            a[2][0] += r2 * xv.x; a[2][1] += r2 * xv.y; a[2][2] += r2 * xv.z; a[2][3] += r2 * xv.w;
            a[3][0] += r3 * xv.x; a[3][1] += r3 * xv.y; a[3][2] += r3 * xv.z; a[3][3] += r3 * xv.w;
            xp += SP_;
        }
        // reduce over c (lane bits 0-1); warps fully active
        const unsigned m = 0xffffffffu;
        #pragma unroll
        for (int h = 0; h < H_; h++)
            #pragma unroll
            for (int j = 0; j < 4; j++) {
                a[h][j] += __shfl_xor_sync(m, a[h][j], 1);
                a[h][j] += __shfl_xor_sync(m, a[h][j], 2);
            }
        if (c == 0 && sq < 21) {
            #pragma unroll
            for (int h = 0; h < H_; h++) {
                float ch = cs[h];
                float4 o;
                float* op = (float*)&o;
                #pragma unroll
                for (int j = 0; j < 4; j++) {
                    int s = sq * 4 + j;
                    float v = (a[h][j] + ch) * 0.0883883476483184405f;
                    if (s == CEN_) v += -1000000.0f;
                    if (s >= 81)  v = -INFINITY;
                    op[j] = v;
                }
                *(float4*)&sc[h * SP_ + sq * 4] = o;
            }
        }
    }
    __syncthreads();

    // ---- softmax: warp h handles row h ----
    const int wid = tid >> 5, lane = tid & 31;
    if (wid < 4) {
        float v0 = sc[wid * SP_ + lane];
        float v1 = sc[wid * SP_ + 32 + lane];
        float v2 = (lane < 20) ? sc[wid * SP_ + 64 + lane] : -INFINITY;
        float mx = fmaxf(v0, fmaxf(v1, v2));
        #pragma unroll
        for (int o = 16; o > 0; o >>= 1) mx = fmaxf(mx, __shfl_xor_sync(0xffffffffu, mx, o));
        float e0 = __expf(v0 - mx), e1 = __expf(v1 - mx);
        float e2 = (lane < 20 && v2 > -INFINITY) ? __expf(v2 - mx) : 0.f;
        float s3 = e0 + e1 + e2;
        #pragma unroll
        for (int o = 16; o > 0; o >>= 1) s3 += __shfl_xor_sync(0xffffffffu, s3, o);
        float rs = 1.f / s3;
        sc[wid * SP_ + lane] = e0 * rs;
        sc[wid * SP_ + 32 + lane] = e1 * rs;
        if (lane < 20) sc[wid * SP_ + 64 + lane] = e2 * rs;
    }
    __syncthreads();

    // ---- y: thread = l, all 4 heads; xs row read exactly once ----
    if (tid < 200) {
        const float* xr = xs + tid * SP_;
        float a0 = 0.f, a1 = 0.f, a2 = 0.f, a3 = 0.f;
        #pragma unroll 7
        for (int c = 0; c < 21; c++) {
            float4 xv = *(const float4*)&xr[c * 4];
            float4 t0 = *(const float4*)&sc[0 * SP_ + c * 4];
            float4 t1 = *(const float4*)&sc[1 * SP_ + c * 4];
            float4 t2 = *(const float4*)&sc[2 * SP_ + c * 4];
            float4 t3 = *(const float4*)&sc[3 * SP_ + c * 4];
            a0 += t0.x * xv.x + t0.y * xv.y + t0.z * xv.z + t0.w * xv.w;
            a1 += t1.x * xv.x + t1.y * xv.y + t1.z * xv.z + t1.w * xv.w;
            a2 += t2.x * xv.x + t2.y * xv.y + t2.z * xv.z + t2.w * xv.w;
            a3 += t3.x * xv.x + t3.y * xv.y + t3.z * xv.z + t3.w * xv.w;
        }
        float* Yb = g_Y + b * 800;
        Yb[tid] = a0; Yb[200 + tid] = a1; Yb[400 + tid] = a2; Yb[600 + tid] = a3;
    }
}

// ============================================================
// ksur: Wvs padded to stride 201 (conflict-free reads)
// grid (128,4), block 256, dyn smem = 20032 floats (80128 B)
// ============================================================
__global__ void __launch_bounds__(256, 2) ksur(const float* __restrict__ Wv,
                                               const float* __restrict__ bv)
{
    extern __shared__ float sm[];
    float* YT  = sm;            // [200][68]
    float* Wvs = sm + 13600;    // [32][201] padded
    const int tid = threadIdx.x;
    const int b0 = blockIdx.x * 64;
    const int h  = blockIdx.y;
    const int lane = tid & 31, w = tid >> 5;

    for (int rb = 0; rb < 8; rb++) {
        int bb = w * 8 + rb;
        const float* ysrc = g_Y + (size_t)(b0 + bb) * 800 + h * 200;
        #pragma unroll
        for (int t = 0; t < 7; t++) {
            int l = lane + 32 * t;
            if (l < 200) YT[l * 68 + bb] = ysrc[l];
        }
    }
    for (int idx = tid; idx < 32 * 200; idx += 256) {
        int dd = idx / 200, ll = idx - dd * 200;
        Wvs[dd * 201 + ll] = Wv[(size_t)(h * 32) * L_ + idx];
    }
    __syncthreads();

    const int bi = tid & 7;
    const int dj = tid >> 3;
    float acc[8];
    #pragma unroll
    for (int v = 0; v < 8; v++) acc[v] = 0.f;
    for (int l = 0; l < 200; l++) {
        float wv = Wvs[dj * 201 + l];
        float4 y0 = *(const float4*)&YT[l * 68 + bi * 8];
        float4 y1 = *(const float4*)&YT[l * 68 + bi * 8 + 4];
        acc[0] += wv * y0.x; acc[1] += wv * y0.y; acc[2] += wv * y0.z; acc[3] += wv * y0.w;
        acc[4] += wv * y1.x; acc[5] += wv * y1.y; acc[6] += wv * y1.z; acc[7] += wv * y1.w;
    }
    float bvd = bv[h * 32 + dj];
    #pragma unroll
    for (int v = 0; v < 8; v++)
        g_sur[(size_t)(b0 + bi * 8 + v) * D_ + h * 32 + dj] = acc[v] + bvd;
}

// ============================================================
// kgate (unchanged)
// ============================================================
__global__ void __launch_bounds__(256) kgate(const float* __restrict__ Wg,
                                             const float* __restrict__ bg,
                                             float* __restrict__ out)
{
    const int lane = threadIdx.x & 31, w = threadIdx.x >> 5;
    const int b = blockIdx.x * 8 + w;
    float4 c4 = *(const float4*)&g_central[(size_t)b * D_ + lane * 4];
    float4 s4 = *(const float4*)&g_sur[(size_t)b * D_ + lane * 4];
    float4 w4 = *(const float4*)&Wg[lane * 4];
    float dot = (c4.x - s4.x) * w4.x + (c4.y - s4.y) * w4.y +
                (c4.z - s4.z) * w4.z + (c4.w - s4.w) * w4.w;
    #pragma unroll
    for (int o = 16; o > 0; o >>= 1) dot += __shfl_xor_sync(0xffffffffu, dot, o);
    float g = 1.f / (1.f + expf(-(dot + bg[0])));
    float4 o4;
    o4.x = c4.x + g * s4.x; o4.y = c4.y + g * s4.y;
    o4.z = c4.z + g * s4.z; o4.w = c4.w + g * s4.w;
    *(float4*)&out[(size_t)b * D_ + lane * 4] = o4;
}

extern "C" void kernel_launch(void* const* d_in, const int* in_sizes, int n_in,
                              void* d_out, int out_size)
{
    const float* x  = (const float*)d_in[0];
    const float* Wk = (const float*)d_in[1];
    const float* bk = (const float*)d_in[2];
    const float* Wv = (const float*)d_in[3];
    const float* bv = (const float*)d_in[4];
    const float* Wq = (const float*)d_in[5];
    const float* bq = (const float*)d_in[6];
    const float* Wg = (const float*)d_in[7];
    const float* bg = (const float*)d_in[8];
    float* out = (float*)d_out;

    cudaFuncSetAttribute(kprep, cudaFuncAttributeMaxDynamicSharedMemorySize, 105472);
    cudaFuncSetAttribute(kmain, cudaFuncAttributeMaxDynamicSharedMemorySize, 71760);
    cudaFuncSetAttribute(ksur,  cudaFuncAttributeMaxDynamicSharedMemorySize, 80128);

    // two no-op launches: keep ncu's -s 5 window on kmain (slot 6)
    knop<<<1, 32>>>();
    knop<<<1, 32>>>();
    kprep<<<128, 256, 105472>>>(x, Wk, bk, Wv, bv, Wq, bq);
    kmain<<<8192, 256, 71760>>>(x);
    ksur<<<dim3(128, 4), 256, 80128>>>(Wv, bv);
    kgate<<<1024, 256>>>(Wg, bg, out);
}